// round 2
// baseline (speedup 1.0000x reference)
#include <cuda_runtime.h>

// ComplexityAnalyzer: per-image 64-bin histogram + L1 normalize + 64->32->128 MLP.
// Inputs (metadata order): grad_map [128*512*512] f32, W1 [32*64], b1 [32],
//                          W2 [128*32], b2 [128]. Output: [128*128] f32.

#define THREADS 1024
#define WARPS   32
#define NPAD    66          // 65 live bins (0..63 + catch bin 64), padded stride

__global__ __launch_bounds__(THREADS, 1)
void ca_hist_mlp_kernel(const float* __restrict__ grad,
                        const float* __restrict__ W1, const float* __restrict__ b1,
                        const float* __restrict__ W2, const float* __restrict__ b2,
                        float* __restrict__ out)
{
    __shared__ unsigned int hist[WARPS * NPAD];   // 8448 B
    __shared__ float fh[64];
    __shared__ float hmid[32];
    __shared__ float inv_s;

    const int tid = threadIdx.x;
    const int wid = tid >> 5;
    const int img = blockIdx.x;

    // Zero per-warp histograms
    #pragma unroll
    for (int i = tid; i < WARPS * NPAD; i += THREADS)
        hist[i] = 0u;
    __syncthreads();

    unsigned int* myh = hist + wid * NPAD;
    const float4* src = (const float4*)(grad + (size_t)img * 262144u);

    const float scale = 64.0f / 255.0f;
    const float magic = 8388608.0f;  // 2^23

    // 512*512 = 262144 elems = 65536 float4; 1024 threads * 64 iters
    #pragma unroll 4
    for (int it = 0; it < 64; ++it) {
        float4 v = __ldg(&src[it * THREADS + tid]);
        float p0, p1, p2, p3;
        // fma.rz: exact product + 2^23, truncate -> mantissa low bits = floor(v*scale)
        asm("fma.rz.f32 %0, %1, %2, %3;" : "=f"(p0) : "f"(v.x), "f"(scale), "f"(magic));
        asm("fma.rz.f32 %0, %1, %2, %3;" : "=f"(p1) : "f"(v.y), "f"(scale), "f"(magic));
        asm("fma.rz.f32 %0, %1, %2, %3;" : "=f"(p2) : "f"(v.z), "f"(scale), "f"(magic));
        asm("fma.rz.f32 %0, %1, %2, %3;" : "=f"(p3) : "f"(v.w), "f"(scale), "f"(magic));
        unsigned i0 = min(__float_as_uint(p0) & 0x7Fu, 64u);
        unsigned i1 = min(__float_as_uint(p1) & 0x7Fu, 64u);
        unsigned i2 = min(__float_as_uint(p2) & 0x7Fu, 64u);
        unsigned i3 = min(__float_as_uint(p3) & 0x7Fu, 64u);
        atomicAdd(&myh[i0], 1u);
        atomicAdd(&myh[i1], 1u);
        atomicAdd(&myh[i2], 1u);
        atomicAdd(&myh[i3], 1u);
    }
    __syncthreads();

    // Reduce 32 warp histograms -> 64 bins (fold catch bin 64 into 63: histc puts v==VMAX in last bin)
    if (tid < 64) {
        unsigned s = 0;
        #pragma unroll
        for (int w = 0; w < WARPS; ++w)
            s += hist[w * NPAD + tid];
        if (tid == 63) {
            #pragma unroll
            for (int w = 0; w < WARPS; ++w)
                s += hist[w * NPAD + 64];
        }
        fh[tid] = (float)s;
    }
    __syncthreads();

    // L1 norm denominator
    if (tid < 32) {
        float s = fh[tid] + fh[tid + 32];
        #pragma unroll
        for (int off = 16; off > 0; off >>= 1)
            s += __shfl_down_sync(0xFFFFFFFFu, s, off);
        if (tid == 0) inv_s = 1.0f / fmaxf(s, 1e-12f);
    }
    __syncthreads();
    if (tid < 64) fh[tid] *= inv_s;
    __syncthreads();

    // Layer 1: h[j] = relu(sum_b fh[b] * W1[j,b] + b1[j]), j < 32
    if (tid < 32) {
        float acc = b1[tid];
        const float* w = W1 + tid * 64;
        #pragma unroll
        for (int b = 0; b < 64; ++b) acc = fmaf(fh[b], w[b], acc);
        hmid[tid] = fmaxf(acc, 0.0f);
    }
    __syncthreads();

    // Layer 2: out[i] = sum_j h[j] * W2[i,j] + b2[i], i < 128
    if (tid < 128) {
        float acc = b2[tid];
        const float* w = W2 + tid * 32;
        #pragma unroll
        for (int j = 0; j < 32; ++j) acc = fmaf(hmid[j], w[j], acc);
        out[img * 128 + tid] = acc;
    }
}

extern "C" void kernel_launch(void* const* d_in, const int* in_sizes, int n_in,
                              void* d_out, int out_size) {
    const float* grad = (const float*)d_in[0];
    const float* W1   = (const float*)d_in[1];
    const float* b1   = (const float*)d_in[2];
    const float* W2   = (const float*)d_in[3];
    const float* b2   = (const float*)d_in[4];
    float* out = (float*)d_out;

    int B = in_sizes[0] / (512 * 512);
    ca_hist_mlp_kernel<<<B, THREADS>>>(grad, W1, b1, W2, b2, out);
}